// round 7
// baseline (speedup 1.0000x reference)
#include <cuda_runtime.h>

#define N_NODES 40000
#define N_EDGES 640000

// Scratch (allocation-free rule: __device__ globals)
__device__ float g_sv[N_NODES * 128];    // lin1 output: [s(32) | vx(32) | vy(32) | vz(32)]
// edge aggregation, quad-interleaved: acc[node][u][c], u in [0,64), c=(s,vx,vy,vz)
__device__ float g_acc[N_NODES * 256];

__device__ __forceinline__ float silu_n(float x) {
    return (x / (1.0f + __expf(-x))) * 1.6791767923989418f;
}

// ---- f32x2 packed helpers (Blackwell) -------------------------------------
__device__ __forceinline__ unsigned long long pk(float a, float b) {
    unsigned long long r;
    asm("mov.b64 %0, {%1,%2};" : "=l"(r) : "f"(a), "f"(b));
    return r;
}
__device__ __forceinline__ void fma2(unsigned long long& d,
                                     unsigned long long a, unsigned long long b) {
    asm("fma.rn.f32x2 %0, %1, %2, %0;" : "+l"(d) : "l"(a), "l"(b));
}
__device__ __forceinline__ float2 unpk(unsigned long long v) {
    float2 r;
    asm("mov.b64 {%0,%1}, %2;" : "=f"(r.x), "=f"(r.y) : "l"(v));
    return r;
}
__device__ __forceinline__ void red4(float* p, float a, float b, float c, float d) {
    asm volatile("red.global.add.v4.f32 [%0], {%1,%2,%3,%4};"
                 :: "l"(p), "f"(a), "f"(b), "f"(c), "f"(d) : "memory");
}

// ---------------------------------------------------------------------------
// K1: lin1 (+ zero g_acc)
// ---------------------------------------------------------------------------
__global__ void lin1_kernel(const float* __restrict__ ni,
                            const float* __restrict__ w1s,
                            const float* __restrict__ w1v) {
    __shared__ float sWs[1024], sWv[1024];
    __shared__ float srow[8][128];
    int tid = threadIdx.x;

    // zero this block's slice of g_acc (2 float4 per thread)
    {
        float4 z = make_float4(0.f, 0.f, 0.f, 0.f);
        size_t base = (size_t)blockIdx.x * 512;   // float4 units
        ((float4*)g_acc)[base + tid]       = z;
        ((float4*)g_acc)[base + 256 + tid] = z;
    }

    const float sc = 0.17677669529663687f;  // 1/sqrt(32)
    for (int i = tid; i < 1024; i += 256) { sWs[i] = w1s[i] * sc; sWv[i] = w1v[i] * sc; }
    __syncthreads();

    int warp = tid >> 5, lane = tid & 31;
    int node = blockIdx.x * 8 + warp;

    ((float4*)srow[warp])[lane] = ((const float4*)(ni + (size_t)node * 128))[lane];
    __syncwarp();

    float s = 0.f, v0 = 0.f, v1 = 0.f, v2 = 0.f;
#pragma unroll
    for (int u = 0; u < 32; u++) {
        float su = srow[warp][u];
        float a0 = srow[warp][32 + u * 3 + 0];
        float a1 = srow[warp][32 + u * 3 + 1];
        float a2 = srow[warp][32 + u * 3 + 2];
        float ws = sWs[u * 32 + lane];
        float wv = sWv[u * 32 + lane];
        s  = fmaf(su, ws, s);
        v0 = fmaf(a0, wv, v0);
        v1 = fmaf(a1, wv, v1);
        v2 = fmaf(a2, wv, v2);
    }
    float* o = g_sv + (size_t)node * 128;
    o[lane]      = s;
    o[32 + lane] = v0;
    o[64 + lane] = v1;
    o[96 + lane] = v2;
}

// ---------------------------------------------------------------------------
// K2: edge kernel — R2 structure, ONE change: h staged DUPLICATED in shared
// so Phase B feeds fma.rn.f32x2 straight from LDS.128 (no pk MOVs).
// Dynamic smem: sF1(512) | sF2p(8192) | hdup(4 warps x 64 rows x 20 floats).
// ---------------------------------------------------------------------------
#define EPW 8
#define HS_STRIDE 20   // 80B rows: 16B-aligned, conflict-free staging
#define EDGE_SMEM_FLOATS (512 + 8192 + 4 * 64 * HS_STRIDE)

__global__ void __launch_bounds__(128, 4)
edge_kernel(const int*    __restrict__ esrc,
            const int*    __restrict__ edst,
            const float4* __restrict__ eattr,
            const float4* __restrict__ escal,
            const float*  __restrict__ fw1,
            const float*  __restrict__ fw2) {
    extern __shared__ float smem[];
    float* sF1    = smem;              // fc_w1 / sqrt(8), [i][64]
    float* sF2p   = smem + 512;        // fc_w2 / 8, packed [j][lane][4]
    float* h_base = smem + 512 + 8192; // duplicated h
    int tid = threadIdx.x;
    for (int i = tid; i < 512; i += 128) sF1[i] = fw1[i] * 0.3535533905932738f;
    for (int i = tid; i < 8192; i += 128) {
        int j = i >> 7;            // 0..63
        int r = i & 127;
        int l = r >> 2, k = r & 3; // lane, output-block
        sF2p[i] = fw2[j * 128 + k * 32 + l] * 0.125f;
    }
    __syncthreads();

    int lane = tid & 31, warp = tid >> 5;
    float* hs = h_base + warp * (64 * HS_STRIDE);
    int wg = blockIdx.x * 4 + warp;
    int nw = gridDim.x * 4;
    const int ngroups = N_EDGES / EPW;

    for (int g = wg; g < ngroups; g += nw) {
        int e0 = g * EPW;
        int src[EPW], dst[EPW];
        float es[EPW], evx[EPW], evy[EPW], evz[EPW];
        float h0[EPW], h1[EPW];

        // Phase A: loads + first MLP layer (lane computes h[lane], h[lane+32])
#pragma unroll
        for (int e = 0; e < EPW; e++) {
            int ed = e0 + e;
            src[e] = esrc[ed];
            dst[e] = edst[ed];
            float4 ea = eattr[ed];
            es[e] = ea.x; evx[e] = ea.y; evy[e] = ea.z; evz[e] = ea.w;
            float4 sA = escal[ed * 2 + 0];
            float4 sB = escal[ed * 2 + 1];
            float sc8[8] = {sA.x, sA.y, sA.z, sA.w, sB.x, sB.y, sB.z, sB.w};
            float a0 = 0.f, a1 = 0.f;
#pragma unroll
            for (int i = 0; i < 8; i++) {
                a0 = fmaf(sc8[i], sF1[i * 64 + lane],      a0);
                a1 = fmaf(sc8[i], sF1[i * 64 + 32 + lane], a1);
            }
            h0[e] = silu_n(a0);
            h1[e] = silu_n(a1);
        }
        __syncwarp();  // previous iteration's readers of hs are done
        // stage DUPLICATED h: row j=lane gets (h0[e],h0[e]) pairs, row 32+lane h1
        {
            float* r0 = hs + lane * HS_STRIDE;
            ((float4*)r0)[0] = make_float4(h0[0], h0[0], h0[1], h0[1]);
            ((float4*)r0)[1] = make_float4(h0[2], h0[2], h0[3], h0[3]);
            ((float4*)r0)[2] = make_float4(h0[4], h0[4], h0[5], h0[5]);
            ((float4*)r0)[3] = make_float4(h0[6], h0[6], h0[7], h0[7]);
            float* r1 = hs + (32 + lane) * HS_STRIDE;
            ((float4*)r1)[0] = make_float4(h1[0], h1[0], h1[1], h1[1]);
            ((float4*)r1)[1] = make_float4(h1[2], h1[2], h1[3], h1[3]);
            ((float4*)r1)[2] = make_float4(h1[4], h1[4], h1[5], h1[5]);
            ((float4*)r1)[3] = make_float4(h1[6], h1[6], h1[7], h1[7]);
        }
        __syncwarp();

        // Phase B: layer 2 with packed f32x2 FMA, zero packing MOVs.
        unsigned long long w01[EPW], w23[EPW];
#pragma unroll
        for (int e = 0; e < EPW; e++) { w01[e] = 0ull; w23[e] = 0ull; }
#pragma unroll 8
        for (int j = 0; j < 64; j++) {
            float4 bw = ((const float4*)sF2p)[j * 32 + lane];  // per-lane weights
            unsigned long long b01 = pk(bw.x, bw.y);           // reg-pair no-op
            unsigned long long b23 = pk(bw.z, bw.w);           // reg-pair no-op
            const ulonglong2* hd = (const ulonglong2*)(hs + j * HS_STRIDE);
            ulonglong2 q0 = hd[0];   // (h0,h0),(h1,h1)  broadcast LDS.128
            ulonglong2 q1 = hd[1];
            ulonglong2 q2 = hd[2];
            ulonglong2 q3 = hd[3];
            fma2(w01[0], q0.x, b01); fma2(w23[0], q0.x, b23);
            fma2(w01[1], q0.y, b01); fma2(w23[1], q0.y, b23);
            fma2(w01[2], q1.x, b01); fma2(w23[2], q1.x, b23);
            fma2(w01[3], q1.y, b01); fma2(w23[3], q1.y, b23);
            fma2(w01[4], q2.x, b01); fma2(w23[4], q2.x, b23);
            fma2(w01[5], q2.y, b01); fma2(w23[5], q2.y, b23);
            fma2(w01[6], q3.x, b01); fma2(w23[6], q3.x, b23);
            fma2(w01[7], q3.y, b01); fma2(w23[7], q3.y, b23);
        }

        // Phase C: gather src (L2-resident), tensor product, vector scatter-add
#pragma unroll
        for (int e = 0; e < EPW; e++) {
            const float* r = g_sv + (size_t)src[e] * 128;
            float se = r[lane];
            float vx = r[32 + lane];
            float vy = r[64 + lane];
            float vz = r[96 + lane];
            float2 a01 = unpk(w01[e]);  // (w0, w1)
            float2 a23 = unpk(w23[e]);  // (w2, w3)
            float dotv = fmaf(vx, evx[e], fmaf(vy, evy[e], vz * evz[e]));
            float ms0 = a01.x * se * es[e];
            float ms1 = a23.y * dotv * 0.5773502691896258f;  // 1/sqrt(3)
            float aa  = a01.y * se;
            float bb  = a23.x * es[e];
            float* ar = g_acc + (size_t)dst[e] * 256;
            red4(ar + lane * 4,       ms0, aa * evx[e], aa * evy[e], aa * evz[e]);
            red4(ar + 128 + lane * 4, ms1, bb * vx,     bb * vy,     bb * vz);
        }
    }
}

// ---------------------------------------------------------------------------
// K3: lin2 — EXACT R2 version (measured best: 51us). Grid N/4, block 256.
// ---------------------------------------------------------------------------
__global__ void __launch_bounds__(256, 2)
lin2_kernel(const float* __restrict__ w2s,
            const float* __restrict__ w2v,
            float* __restrict__ out) {
    __shared__ float rows[4][256];       // 4 node rows, quad-interleaved
    __shared__ float part[4][2][128];    // partials [slot][half][lane*4]
    int tid = threadIdx.x;
    int warp = tid >> 5, lane = tid & 31;
    int slot = warp >> 1, p = warp & 1;

    const float sc = 0.03125f;  // (1/sqrt(16)) / sqrt(64)
    unsigned long long wreg[32];
#pragma unroll
    for (int i = 0; i < 32; i++) {
        int u = (p << 5) + i;
        wreg[i] = pk(w2s[u * 32 + lane] * sc, w2v[u * 32 + lane] * sc);
    }

    int node0 = blockIdx.x * 4;
    ((float4*)rows)[tid] = ((const float4*)(g_acc + (size_t)node0 * 256))[tid];
    __syncthreads();

    unsigned long long a0 = 0ull, a1 = 0ull;   // (s,v0), (v1,v2)
    const float4* qr = (const float4*)rows[slot] + (p << 5);
#pragma unroll 8
    for (int i = 0; i < 32; i++) {
        float4 q = qr[i];
        float2 w = unpk(wreg[i]);
        fma2(a0, pk(q.x, q.y), wreg[i]);
        fma2(a1, pk(q.z, q.w), pk(w.y, w.y));
    }
    float2 r0 = unpk(a0), r1 = unpk(a1);
    ((float4*)part[slot][p])[lane] = make_float4(r0.x, r0.y, r1.x, r1.y);
    __syncthreads();

    if (p == 0) {
        float4 A = ((const float4*)part[slot][0])[lane];
        float4 B = ((const float4*)part[slot][1])[lane];
        float* o = out + (size_t)(node0 + slot) * 128;
        o[lane]              = A.x + B.x;
        o[32 + lane * 3 + 0] = A.y + B.y;
        o[32 + lane * 3 + 1] = A.z + B.z;
        o[32 + lane * 3 + 2] = A.w + B.w;
    }
}

// ---------------------------------------------------------------------------
extern "C" void kernel_launch(void* const* d_in, const int* in_sizes, int n_in,
                              void* d_out, int out_size) {
    const float* node_input = (const float*)d_in[0];
    const int*   esrc  = (const int*)d_in[2];
    const int*   edst  = (const int*)d_in[3];
    const float* eattr = (const float*)d_in[4];
    const float* escal = (const float*)d_in[5];
    const float* w1s   = (const float*)d_in[6];
    const float* w1v   = (const float*)d_in[7];
    const float* fw1   = (const float*)d_in[8];
    const float* fw2   = (const float*)d_in[9];
    const float* w2s   = (const float*)d_in[10];
    const float* w2v   = (const float*)d_in[11];
    float* out = (float*)d_out;

    static bool attr_set = false;
    if (!attr_set) {
        cudaFuncSetAttribute(edge_kernel,
                             cudaFuncAttributeMaxDynamicSharedMemorySize,
                             EDGE_SMEM_FLOATS * 4);
        attr_set = true;
    }

    lin1_kernel<<<N_NODES / 8, 256>>>(node_input, w1s, w1v);
    edge_kernel<<<592, 128, EDGE_SMEM_FLOATS * 4>>>(
        esrc, edst, (const float4*)eattr, (const float4*)escal, fw1, fw2);
    lin2_kernel<<<N_NODES / 4, 256>>>(w2s, w2v, out);
}

// round 8
// speedup vs baseline: 1.1015x; 1.1015x over previous
#include <cuda_runtime.h>

#define N_NODES 40000
#define N_EDGES 640000

// Scratch (allocation-free rule: __device__ globals)
// lin1 output, QUAD layout: g_sv[node][lane] = (s, vx, vy, vz)  (float4)
__device__ float g_sv[N_NODES * 128];
// edge aggregation, quad-interleaved: acc[node][u][c], u in [0,64), c=(s,vx,vy,vz)
__device__ float g_acc[N_NODES * 256];

__device__ __forceinline__ float silu_n(float x) {
    return (x / (1.0f + __expf(-x))) * 1.6791767923989418f;
}

// ---- f32x2 packed helpers (Blackwell) -------------------------------------
__device__ __forceinline__ unsigned long long pk(float a, float b) {
    unsigned long long r;
    asm("mov.b64 %0, {%1,%2};" : "=l"(r) : "f"(a), "f"(b));
    return r;
}
__device__ __forceinline__ void fma2(unsigned long long& d,
                                     unsigned long long a, unsigned long long b) {
    asm("fma.rn.f32x2 %0, %1, %2, %0;" : "+l"(d) : "l"(a), "l"(b));
}
__device__ __forceinline__ float2 unpk(unsigned long long v) {
    float2 r;
    asm("mov.b64 {%0,%1}, %2;" : "=f"(r.x), "=f"(r.y) : "l"(v));
    return r;
}
__device__ __forceinline__ void red4(float* p, float a, float b, float c, float d) {
    asm volatile("red.global.add.v4.f32 [%0], {%1,%2,%3,%4};"
                 :: "l"(p), "f"(a), "f"(b), "f"(c), "f"(d) : "memory");
}

// ---------------------------------------------------------------------------
// K1: lin1 (+ zero g_acc) — writes quad layout (one STG.128 per lane)
// ---------------------------------------------------------------------------
__global__ void lin1_kernel(const float* __restrict__ ni,
                            const float* __restrict__ w1s,
                            const float* __restrict__ w1v) {
    __shared__ float sWs[1024], sWv[1024];
    __shared__ float srow[8][128];
    int tid = threadIdx.x;

    // zero this block's slice of g_acc (2 float4 per thread)
    {
        float4 z = make_float4(0.f, 0.f, 0.f, 0.f);
        size_t base = (size_t)blockIdx.x * 512;   // float4 units
        ((float4*)g_acc)[base + tid]       = z;
        ((float4*)g_acc)[base + 256 + tid] = z;
    }

    const float sc = 0.17677669529663687f;  // 1/sqrt(32)
    for (int i = tid; i < 1024; i += 256) { sWs[i] = w1s[i] * sc; sWv[i] = w1v[i] * sc; }
    __syncthreads();

    int warp = tid >> 5, lane = tid & 31;
    int node = blockIdx.x * 8 + warp;

    ((float4*)srow[warp])[lane] = ((const float4*)(ni + (size_t)node * 128))[lane];
    __syncwarp();

    float s = 0.f, v0 = 0.f, v1 = 0.f, v2 = 0.f;
#pragma unroll
    for (int u = 0; u < 32; u++) {
        float su = srow[warp][u];
        float a0 = srow[warp][32 + u * 3 + 0];
        float a1 = srow[warp][32 + u * 3 + 1];
        float a2 = srow[warp][32 + u * 3 + 2];
        float ws = sWs[u * 32 + lane];
        float wv = sWv[u * 32 + lane];
        s  = fmaf(su, ws, s);
        v0 = fmaf(a0, wv, v0);
        v1 = fmaf(a1, wv, v1);
        v2 = fmaf(a2, wv, v2);
    }
    // quad store: (s, vx, vy, vz) per lane
    ((float4*)(g_sv + (size_t)node * 128))[lane] = make_float4(s, v0, v1, v2);
}

// ---------------------------------------------------------------------------
// K2: edge kernel — R2 structure; ONE change vs R2: Phase-C gather is a
// single LDG.128 per edge (quad g_sv layout).
// ---------------------------------------------------------------------------
#define EPW 8
__global__ void __launch_bounds__(128, 4)
edge_kernel(const int*    __restrict__ esrc,
            const int*    __restrict__ edst,
            const float4* __restrict__ eattr,
            const float4* __restrict__ escal,
            const float*  __restrict__ fw1,
            const float*  __restrict__ fw2) {
    __shared__ float sF1[512];        // fc_w1 / sqrt(8), [i][64]
    __shared__ float sF2p[8192];      // fc_w2 / 8, packed [j][lane][4]
    __shared__ float h_sh[4][64 * EPW];  // per-warp h, [j][e]
    int tid = threadIdx.x;
    for (int i = tid; i < 512; i += 128) sF1[i] = fw1[i] * 0.3535533905932738f;
    for (int i = tid; i < 8192; i += 128) {
        int j = i >> 7;            // 0..63
        int r = i & 127;
        int l = r >> 2, k = r & 3; // lane, output-block
        sF2p[i] = fw2[j * 128 + k * 32 + l] * 0.125f;
    }
    __syncthreads();

    int lane = tid & 31, warp = tid >> 5;
    float* hs = h_sh[warp];
    int wg = blockIdx.x * 4 + warp;
    int nw = gridDim.x * 4;
    const int ngroups = N_EDGES / EPW;

    for (int g = wg; g < ngroups; g += nw) {
        int e0 = g * EPW;
        int src[EPW], dst[EPW];
        float es[EPW], evx[EPW], evy[EPW], evz[EPW];
        float h0[EPW], h1[EPW];

        // Phase A: loads + first MLP layer (lane computes h[lane], h[lane+32])
#pragma unroll
        for (int e = 0; e < EPW; e++) {
            int ed = e0 + e;
            src[e] = esrc[ed];
            dst[e] = edst[ed];
            float4 ea = eattr[ed];
            es[e] = ea.x; evx[e] = ea.y; evy[e] = ea.z; evz[e] = ea.w;
            float4 sA = escal[ed * 2 + 0];
            float4 sB = escal[ed * 2 + 1];
            float sc8[8] = {sA.x, sA.y, sA.z, sA.w, sB.x, sB.y, sB.z, sB.w};
            float a0 = 0.f, a1 = 0.f;
#pragma unroll
            for (int i = 0; i < 8; i++) {
                a0 = fmaf(sc8[i], sF1[i * 64 + lane],      a0);
                a1 = fmaf(sc8[i], sF1[i * 64 + 32 + lane], a1);
            }
            h0[e] = silu_n(a0);
            h1[e] = silu_n(a1);
        }
        __syncwarp();  // previous iteration's readers of hs are done
        // stage h into shared: row j=lane gets h0, row j=32+lane gets h1
        ((float4*)hs)[lane * 2 + 0]      = make_float4(h0[0], h0[1], h0[2], h0[3]);
        ((float4*)hs)[lane * 2 + 1]      = make_float4(h0[4], h0[5], h0[6], h0[7]);
        ((float4*)hs)[64 + lane * 2 + 0] = make_float4(h1[0], h1[1], h1[2], h1[3]);
        ((float4*)hs)[64 + lane * 2 + 1] = make_float4(h1[4], h1[5], h1[6], h1[7]);
        __syncwarp();

        // Phase B: layer 2 with packed f32x2 FMA. w01[e]=(w0,w1), w23[e]=(w2,w3)
        unsigned long long w01[EPW], w23[EPW];
#pragma unroll
        for (int e = 0; e < EPW; e++) { w01[e] = 0ull; w23[e] = 0ull; }
#pragma unroll 8
        for (int j = 0; j < 64; j++) {
            float4 bw = ((const float4*)sF2p)[j * 32 + lane];  // per-lane weights
            unsigned long long b01 = pk(bw.x, bw.y);
            unsigned long long b23 = pk(bw.z, bw.w);
            float4 hA = ((const float4*)hs)[j * 2 + 0];  // broadcast h, e0..3
            float4 hB = ((const float4*)hs)[j * 2 + 1];  // e4..7
            float hv[EPW] = {hA.x, hA.y, hA.z, hA.w, hB.x, hB.y, hB.z, hB.w};
#pragma unroll
            for (int e = 0; e < EPW; e++) {
                unsigned long long hh = pk(hv[e], hv[e]);
                fma2(w01[e], hh, b01);
                fma2(w23[e], hh, b23);
            }
        }

        // Phase C: single LDG.128 gather per edge (quad layout), tensor
        // product, vector scatter-add.
#pragma unroll
        for (int e = 0; e < EPW; e++) {
            float4 q = ((const float4*)(g_sv + (size_t)src[e] * 128))[lane];
            float se = q.x, vx = q.y, vy = q.z, vz = q.w;
            float2 a01 = unpk(w01[e]);  // (w0, w1)
            float2 a23 = unpk(w23[e]);  // (w2, w3)
            float dotv = fmaf(vx, evx[e], fmaf(vy, evy[e], vz * evz[e]));
            float ms0 = a01.x * se * es[e];
            float ms1 = a23.y * dotv * 0.5773502691896258f;  // 1/sqrt(3)
            float aa  = a01.y * se;
            float bb  = a23.x * es[e];
            float* ar = g_acc + (size_t)dst[e] * 256;
            red4(ar + lane * 4,       ms0, aa * evx[e], aa * evy[e], aa * evz[e]);
            red4(ar + 128 + lane * 4, ms1, bb * vx,     bb * vy,     bb * vz);
        }
    }
}

// ---------------------------------------------------------------------------
// K3: lin2 — EXACT R2 version (measured best: 51us). Grid N/4, block 256.
// ---------------------------------------------------------------------------
__global__ void __launch_bounds__(256, 2)
lin2_kernel(const float* __restrict__ w2s,
            const float* __restrict__ w2v,
            float* __restrict__ out) {
    __shared__ float rows[4][256];       // 4 node rows, quad-interleaved
    __shared__ float part[4][2][128];    // partials [slot][half][lane*4]
    int tid = threadIdx.x;
    int warp = tid >> 5, lane = tid & 31;
    int slot = warp >> 1, p = warp & 1;

    const float sc = 0.03125f;  // (1/sqrt(16)) / sqrt(64)
    unsigned long long wreg[32];
#pragma unroll
    for (int i = 0; i < 32; i++) {
        int u = (p << 5) + i;
        wreg[i] = pk(w2s[u * 32 + lane] * sc, w2v[u * 32 + lane] * sc);
    }

    int node0 = blockIdx.x * 4;
    ((float4*)rows)[tid] = ((const float4*)(g_acc + (size_t)node0 * 256))[tid];
    __syncthreads();

    unsigned long long a0 = 0ull, a1 = 0ull;   // (s,v0), (v1,v2)
    const float4* qr = (const float4*)rows[slot] + (p << 5);
#pragma unroll 8
    for (int i = 0; i < 32; i++) {
        float4 q = qr[i];
        float2 w = unpk(wreg[i]);
        fma2(a0, pk(q.x, q.y), wreg[i]);
        fma2(a1, pk(q.z, q.w), pk(w.y, w.y));
    }
    float2 r0 = unpk(a0), r1 = unpk(a1);
    ((float4*)part[slot][p])[lane] = make_float4(r0.x, r0.y, r1.x, r1.y);
    __syncthreads();

    if (p == 0) {
        float4 A = ((const float4*)part[slot][0])[lane];
        float4 B = ((const float4*)part[slot][1])[lane];
        float* o = out + (size_t)(node0 + slot) * 128;
        o[lane]              = A.x + B.x;
        o[32 + lane * 3 + 0] = A.y + B.y;
        o[32 + lane * 3 + 1] = A.z + B.z;
        o[32 + lane * 3 + 2] = A.w + B.w;
    }
}

// ---------------------------------------------------------------------------
extern "C" void kernel_launch(void* const* d_in, const int* in_sizes, int n_in,
                              void* d_out, int out_size) {
    const float* node_input = (const float*)d_in[0];
    const int*   esrc  = (const int*)d_in[2];
    const int*   edst  = (const int*)d_in[3];
    const float* eattr = (const float*)d_in[4];
    const float* escal = (const float*)d_in[5];
    const float* w1s   = (const float*)d_in[6];
    const float* w1v   = (const float*)d_in[7];
    const float* fw1   = (const float*)d_in[8];
    const float* fw2   = (const float*)d_in[9];
    const float* w2s   = (const float*)d_in[10];
    const float* w2v   = (const float*)d_in[11];
    float* out = (float*)d_out;

    lin1_kernel<<<N_NODES / 8, 256>>>(node_input, w1s, w1v);
    edge_kernel<<<592, 128>>>(esrc, edst, (const float4*)eattr,
                              (const float4*)escal, fw1, fw2);
    lin2_kernel<<<N_NODES / 4, 256>>>(w2s, w2v, out);
}

// round 9
// speedup vs baseline: 1.2031x; 1.0923x over previous
#include <cuda_runtime.h>

#define N_NODES 40000
#define N_EDGES 640000

// Scratch (allocation-free rule: __device__ globals)
// lin1 output, QUAD layout: g_sv[node][lane] = (s, vx, vy, vz)  (float4)
__device__ float g_sv[N_NODES * 128];
// edge aggregation, quad-interleaved: acc[node][u][c], u in [0,64), c=(s,vx,vy,vz)
__device__ float g_acc[N_NODES * 256];

__device__ __forceinline__ float silu_n(float x) {
    return (x / (1.0f + __expf(-x))) * 1.6791767923989418f;
}

// ---- f32x2 packed helpers (Blackwell) -------------------------------------
__device__ __forceinline__ unsigned long long pk(float a, float b) {
    unsigned long long r;
    asm("mov.b64 %0, {%1,%2};" : "=l"(r) : "f"(a), "f"(b));
    return r;
}
__device__ __forceinline__ void fma2(unsigned long long& d,
                                     unsigned long long a, unsigned long long b) {
    asm("fma.rn.f32x2 %0, %1, %2, %0;" : "+l"(d) : "l"(a), "l"(b));
}
__device__ __forceinline__ float2 unpk(unsigned long long v) {
    float2 r;
    asm("mov.b64 {%0,%1}, %2;" : "=f"(r.x), "=f"(r.y) : "l"(v));
    return r;
}
__device__ __forceinline__ void red4(float* p, float a, float b, float c, float d) {
    asm volatile("red.global.add.v4.f32 [%0], {%1,%2,%3,%4};"
                 :: "l"(p), "f"(a), "f"(b), "f"(c), "f"(d) : "memory");
}

// ---------------------------------------------------------------------------
// K1: lin1 (+ zero g_acc) — writes quad layout (one STG.128 per lane)
// ---------------------------------------------------------------------------
__global__ void lin1_kernel(const float* __restrict__ ni,
                            const float* __restrict__ w1s,
                            const float* __restrict__ w1v) {
    __shared__ float sWs[1024], sWv[1024];
    __shared__ float srow[8][128];
    int tid = threadIdx.x;

    // zero this block's slice of g_acc (2 float4 per thread)
    {
        float4 z = make_float4(0.f, 0.f, 0.f, 0.f);
        size_t base = (size_t)blockIdx.x * 512;   // float4 units
        ((float4*)g_acc)[base + tid]       = z;
        ((float4*)g_acc)[base + 256 + tid] = z;
    }

    const float sc = 0.17677669529663687f;  // 1/sqrt(32)
    for (int i = tid; i < 1024; i += 256) { sWs[i] = w1s[i] * sc; sWv[i] = w1v[i] * sc; }
    __syncthreads();

    int warp = tid >> 5, lane = tid & 31;
    int node = blockIdx.x * 8 + warp;

    ((float4*)srow[warp])[lane] = ((const float4*)(ni + (size_t)node * 128))[lane];
    __syncwarp();

    float s = 0.f, v0 = 0.f, v1 = 0.f, v2 = 0.f;
#pragma unroll
    for (int u = 0; u < 32; u++) {
        float su = srow[warp][u];
        float a0 = srow[warp][32 + u * 3 + 0];
        float a1 = srow[warp][32 + u * 3 + 1];
        float a2 = srow[warp][32 + u * 3 + 2];
        float ws = sWs[u * 32 + lane];
        float wv = sWv[u * 32 + lane];
        s  = fmaf(su, ws, s);
        v0 = fmaf(a0, wv, v0);
        v1 = fmaf(a1, wv, v1);
        v2 = fmaf(a2, wv, v2);
    }
    // quad store: (s, vx, vy, vz) per lane
    ((float4*)(g_sv + (size_t)node * 128))[lane] = make_float4(s, v0, v1, v2);
}

// ---------------------------------------------------------------------------
// K2: edge kernel — R2 structure + quad LDG.128 gather; occupancy 5 blocks/SM.
// ---------------------------------------------------------------------------
#define EPW 8
__global__ void __launch_bounds__(128, 5)
edge_kernel(const int*    __restrict__ esrc,
            const int*    __restrict__ edst,
            const float4* __restrict__ eattr,
            const float4* __restrict__ escal,
            const float*  __restrict__ fw1,
            const float*  __restrict__ fw2) {
    __shared__ float sF1[512];        // fc_w1 / sqrt(8), [i][64]
    __shared__ float sF2p[8192];      // fc_w2 / 8, packed [j][lane][4]
    __shared__ float h_sh[4][64 * EPW];  // per-warp h, [j][e]
    int tid = threadIdx.x;
    for (int i = tid; i < 512; i += 128) sF1[i] = fw1[i] * 0.3535533905932738f;
    for (int i = tid; i < 8192; i += 128) {
        int j = i >> 7;            // 0..63
        int r = i & 127;
        int l = r >> 2, k = r & 3; // lane, output-block
        sF2p[i] = fw2[j * 128 + k * 32 + l] * 0.125f;
    }
    __syncthreads();

    int lane = tid & 31, warp = tid >> 5;
    float* hs = h_sh[warp];
    int wg = blockIdx.x * 4 + warp;
    int nw = gridDim.x * 4;
    const int ngroups = N_EDGES / EPW;

    for (int g = wg; g < ngroups; g += nw) {
        int e0 = g * EPW;
        int src[EPW], dst[EPW];
        float es[EPW], evx[EPW], evy[EPW], evz[EPW];
        float h0[EPW], h1[EPW];

        // Phase A: loads + first MLP layer (lane computes h[lane], h[lane+32])
#pragma unroll
        for (int e = 0; e < EPW; e++) {
            int ed = e0 + e;
            src[e] = esrc[ed];
            dst[e] = edst[ed];
            float4 ea = eattr[ed];
            es[e] = ea.x; evx[e] = ea.y; evy[e] = ea.z; evz[e] = ea.w;
            float4 sA = escal[ed * 2 + 0];
            float4 sB = escal[ed * 2 + 1];
            float sc8[8] = {sA.x, sA.y, sA.z, sA.w, sB.x, sB.y, sB.z, sB.w};
            float a0 = 0.f, a1 = 0.f;
#pragma unroll
            for (int i = 0; i < 8; i++) {
                a0 = fmaf(sc8[i], sF1[i * 64 + lane],      a0);
                a1 = fmaf(sc8[i], sF1[i * 64 + 32 + lane], a1);
            }
            h0[e] = silu_n(a0);
            h1[e] = silu_n(a1);
        }
        __syncwarp();  // previous iteration's readers of hs are done
        // stage h into shared: row j=lane gets h0, row j=32+lane gets h1
        ((float4*)hs)[lane * 2 + 0]      = make_float4(h0[0], h0[1], h0[2], h0[3]);
        ((float4*)hs)[lane * 2 + 1]      = make_float4(h0[4], h0[5], h0[6], h0[7]);
        ((float4*)hs)[64 + lane * 2 + 0] = make_float4(h1[0], h1[1], h1[2], h1[3]);
        ((float4*)hs)[64 + lane * 2 + 1] = make_float4(h1[4], h1[5], h1[6], h1[7]);
        __syncwarp();

        // Phase B: layer 2 with packed f32x2 FMA. w01[e]=(w0,w1), w23[e]=(w2,w3)
        unsigned long long w01[EPW], w23[EPW];
#pragma unroll
        for (int e = 0; e < EPW; e++) { w01[e] = 0ull; w23[e] = 0ull; }
#pragma unroll 8
        for (int j = 0; j < 64; j++) {
            float4 bw = ((const float4*)sF2p)[j * 32 + lane];  // per-lane weights
            unsigned long long b01 = pk(bw.x, bw.y);
            unsigned long long b23 = pk(bw.z, bw.w);
            float4 hA = ((const float4*)hs)[j * 2 + 0];  // broadcast h, e0..3
            float4 hB = ((const float4*)hs)[j * 2 + 1];  // e4..7
            float hv[EPW] = {hA.x, hA.y, hA.z, hA.w, hB.x, hB.y, hB.z, hB.w};
#pragma unroll
            for (int e = 0; e < EPW; e++) {
                unsigned long long hh = pk(hv[e], hv[e]);
                fma2(w01[e], hh, b01);
                fma2(w23[e], hh, b23);
            }
        }

        // Phase C: single LDG.128 gather per edge (quad layout), tensor
        // product, vector scatter-add.
#pragma unroll
        for (int e = 0; e < EPW; e++) {
            float4 q = ((const float4*)(g_sv + (size_t)src[e] * 128))[lane];
            float se = q.x, vx = q.y, vy = q.z, vz = q.w;
            float2 a01 = unpk(w01[e]);  // (w0, w1)
            float2 a23 = unpk(w23[e]);  // (w2, w3)
            float dotv = fmaf(vx, evx[e], fmaf(vy, evy[e], vz * evz[e]));
            float ms0 = a01.x * se * es[e];
            float ms1 = a23.y * dotv * 0.5773502691896258f;  // 1/sqrt(3)
            float aa  = a01.y * se;
            float bb  = a23.x * es[e];
            float* ar = g_acc + (size_t)dst[e] * 256;
            red4(ar + lane * 4,       ms0, aa * evx[e], aa * evy[e], aa * evz[e]);
            red4(ar + 128 + lane * 4, ms1, bb * vx,     bb * vy,     bb * vz);
        }
    }
}

// ---------------------------------------------------------------------------
// K3: lin2 — TRUE R2 version (measured 51us): shared float2 weight pairs,
// grid N/8, one warp per node, quad-interleaved acc input.
// ---------------------------------------------------------------------------
__global__ void lin2_kernel(const float* __restrict__ w2s,
                            const float* __restrict__ w2v,
                            float* __restrict__ out) {
    __shared__ float sW[4096];      // (ws,wv) pairs: [u][lane][2]
    __shared__ float srow[8][256];
    int tid = threadIdx.x;
    const float sc = 0.03125f;      // (1/sqrt(16)) / sqrt(64)
    for (int i = tid; i < 2048; i += 256) {
        sW[i * 2 + 0] = w2s[i] * sc;
        sW[i * 2 + 1] = w2v[i] * sc;
    }
    __syncthreads();

    int warp = tid >> 5, lane = tid & 31;
    int node = blockIdx.x * 8 + warp;

    const float4* ar = (const float4*)(g_acc + (size_t)node * 256);
    ((float4*)srow[warp])[lane]      = ar[lane];
    ((float4*)srow[warp])[lane + 32] = ar[lane + 32];
    __syncwarp();

    unsigned long long acc0 = 0ull, acc1 = 0ull;   // (s,v0), (v1,v2)
#pragma unroll 8
    for (int u = 0; u < 64; u++) {
        float4 q = ((const float4*)srow[warp])[u];        // broadcast (s,vx,vy,vz)
        float2 wsv = ((const float2*)sW)[u * 32 + lane];  // (ws, wv)
        fma2(acc0, pk(q.x, q.y), pk(wsv.x, wsv.y));
        fma2(acc1, pk(q.z, q.w), pk(wsv.y, wsv.y));
    }
    float2 r0 = unpk(acc0), r1 = unpk(acc1);
    float* o = out + (size_t)node * 128;
    o[lane] = r0.x;
    o[32 + lane * 3 + 0] = r0.y;
    o[32 + lane * 3 + 1] = r1.x;
    o[32 + lane * 3 + 2] = r1.y;
}

// ---------------------------------------------------------------------------
extern "C" void kernel_launch(void* const* d_in, const int* in_sizes, int n_in,
                              void* d_out, int out_size) {
    const float* node_input = (const float*)d_in[0];
    const int*   esrc  = (const int*)d_in[2];
    const int*   edst  = (const int*)d_in[3];
    const float* eattr = (const float*)d_in[4];
    const float* escal = (const float*)d_in[5];
    const float* w1s   = (const float*)d_in[6];
    const float* w1v   = (const float*)d_in[7];
    const float* fw1   = (const float*)d_in[8];
    const float* fw2   = (const float*)d_in[9];
    const float* w2s   = (const float*)d_in[10];
    const float* w2v   = (const float*)d_in[11];
    float* out = (float*)d_out;

    lin1_kernel<<<N_NODES / 8, 256>>>(node_input, w1s, w1v);
    edge_kernel<<<740, 128>>>(esrc, edst, (const float4*)eattr,
                              (const float4*)escal, fw1, fw2);
    lin2_kernel<<<N_NODES / 8, 256>>>(w2s, w2v, out);
}